// round 10
// baseline (speedup 1.0000x reference)
#include <cuda_runtime.h>
#include <math.h>

#define B_ 8
#define H_ 96
#define W_ 96
#define O_ 8
#define NCH 32          // h-chunks per b -> 256 CTAs, ~2 CTAs/SM
#define RPC 3           // rows per chunk (32*3 = 96)
#define NACC 60         // 6 C-pairs x 10 Q-pairs

// ---- f32 fast path (vectorized wpix) ----
__device__ __forceinline__ void accumulate_points_f32(
    const float* __restrict__ obj, const float* __restrict__ wpix,
    const float* __restrict__ cam, const float* __restrict__ coordK,
    int b, int ch, int wl, int o, float* acc)
{
    const float a   = -cam[b * 9 + 0];
    const float cb  = -cam[b * 9 + 4];
    const float c02 =  cam[b * 9 + 2];
    const float c12 =  cam[b * 9 + 5];
    const float K00 = coordK[b * 4 + 0];
    const float K01 = coordK[b * 4 + 1];
    const float K10 = coordK[b * 4 + 2];
    const float K11 = coordK[b * 4 + 3];

    float du3[3];
#pragma unroll
    for (int wj = 0; wj < 3; wj++)
        du3[wj] = ((float)(wj * 32 + wl) * K00 + K10) - c02;

#pragma unroll
    for (int hi = 0; hi < RPC; hi++) {
        const int h = ch * RPC + hi;
        const float dv = ((float)h * K01 + K11) - c12;
#pragma unroll
        for (int wj = 0; wj < 3; wj++) {
            const int w = wj * 32 + wl;
            const float du = du3[wj];

            const long idx = (((long)b * H_ + h) * W_ + w) * O_ + o;
            const float* op = obj + idx * 3;
            const float p1 = op[0];
            const float p2 = op[1];
            const float p3 = op[2];
            const float4 wv = *(const float4*)(wpix + idx * 4);

            const float cA0 = wv.x * a;
            const float cB0 = wv.y * cb;
            const float cC0 = wv.x * du + wv.y * dv;
            const float cA1 = wv.z * a;
            const float cB1 = wv.w * cb;
            const float cC1 = wv.z * du + wv.w * dv;

            float C[6];
            C[0] = cA0 * cA0 + cA1 * cA1;
            C[1] = cA0 * cB0 + cA1 * cB1;
            C[2] = cA0 * cC0 + cA1 * cC1;
            C[3] = cB0 * cB0 + cB1 * cB1;
            C[4] = cB0 * cC0 + cB1 * cC1;
            C[5] = cC0 * cC0 + cC1 * cC1;

            float q[9];
            q[0] = p1 * p1; q[1] = p1 * p2; q[2] = p1 * p3;
            q[3] = p2 * p2; q[4] = p2 * p3; q[5] = p3 * p3;
            q[6] = p1;      q[7] = p2;      q[8] = p3;

#pragma unroll
            for (int ci = 0; ci < 6; ci++) {
#pragma unroll
                for (int qi = 0; qi < 9; qi++)
                    acc[ci * 10 + qi] += C[ci] * q[qi];
                acc[ci * 10 + 9] += C[ci];
            }
        }
    }
}

// ---- f64 safety path ----
__device__ __forceinline__ void accumulate_points_f64(
    const double* __restrict__ obj, const double* __restrict__ wpix,
    const double* __restrict__ cam, const double* __restrict__ coordK,
    int b, int ch, int wl, int o, float* acc)
{
    const float a   = -(float)cam[b * 9 + 0];
    const float cb  = -(float)cam[b * 9 + 4];
    const float c02 =  (float)cam[b * 9 + 2];
    const float c12 =  (float)cam[b * 9 + 5];
    const float K00 = (float)coordK[b * 4 + 0];
    const float K01 = (float)coordK[b * 4 + 1];
    const float K10 = (float)coordK[b * 4 + 2];
    const float K11 = (float)coordK[b * 4 + 3];

    float du3[3];
#pragma unroll
    for (int wj = 0; wj < 3; wj++)
        du3[wj] = ((float)(wj * 32 + wl) * K00 + K10) - c02;

#pragma unroll
    for (int hi = 0; hi < RPC; hi++) {
        const int h = ch * RPC + hi;
        const float dv = ((float)h * K01 + K11) - c12;
#pragma unroll
        for (int wj = 0; wj < 3; wj++) {
            const int w = wj * 32 + wl;
            const float du = du3[wj];
            const long idx = (((long)b * H_ + h) * W_ + w) * O_ + o;
            const double* op = obj  + idx * 3;
            const double* wp = wpix + idx * 4;
            const float p1 = (float)op[0], p2 = (float)op[1], p3 = (float)op[2];
            const float w0 = (float)wp[0], w1 = (float)wp[1];
            const float w2 = (float)wp[2], w3 = (float)wp[3];

            const float cA0 = w0 * a;
            const float cB0 = w1 * cb;
            const float cC0 = w0 * du + w1 * dv;
            const float cA1 = w2 * a;
            const float cB1 = w3 * cb;
            const float cC1 = w2 * du + w3 * dv;

            float C[6];
            C[0] = cA0 * cA0 + cA1 * cA1;
            C[1] = cA0 * cB0 + cA1 * cB1;
            C[2] = cA0 * cC0 + cA1 * cC1;
            C[3] = cB0 * cB0 + cB1 * cB1;
            C[4] = cB0 * cC0 + cB1 * cC1;
            C[5] = cC0 * cC0 + cC1 * cC1;

            float q[9];
            q[0] = p1 * p1; q[1] = p1 * p2; q[2] = p1 * p3;
            q[3] = p2 * p2; q[4] = p2 * p3; q[5] = p3 * p3;
            q[6] = p1;      q[7] = p2;      q[8] = p3;

#pragma unroll
            for (int ci = 0; ci < 6; ci++) {
#pragma unroll
                for (int qi = 0; qi < 9; qi++)
                    acc[ci * 10 + qi] += C[ci] * q[qi];
                acc[ci * 10 + 9] += C[ci];
            }
        }
    }
}

__global__ __launch_bounds__(256)
void mtm_onepass_kernel(const void* __restrict__ objv,
                        const void* __restrict__ wpixv,
                        const void* __restrict__ camv,
                        const void* __restrict__ coordKv,
                        float* __restrict__ out)
{
    __shared__ int s_is64;
    const int blk = blockIdx.x;
    const int b  = blk >> 5;       // / NCH
    const int ch = blk & 31;       // % NCH
    const int tid = threadIdx.x;
    const int o  = tid & 7;
    const int wl = tid >> 3;

    // inline dtype probe (f32 vs f64), 256 parallel tests of the big buffer
    if (tid == 0) s_is64 = 0;
    __syncthreads();
    {
        float x = ((const float*)wpixv)[tid];
        if (!(fabsf(x) < 1.0e4f)) atomicOr(&s_is64, 1);
    }
    __syncthreads();
    const int is64 = s_is64;

    float acc[NACC];
#pragma unroll
    for (int i = 0; i < NACC; i++) acc[i] = 0.0f;

    if (is64 == 0) {
        accumulate_points_f32((const float*)objv, (const float*)wpixv,
                              (const float*)camv, (const float*)coordKv,
                              b, ch, wl, o, acc);
    } else {
        accumulate_points_f64((const double*)objv, (const double*)wpixv,
                              (const double*)camv, (const double*)coordKv,
                              b, ch, wl, o, acc);
    }

    // combine the 4 lanes in this warp sharing the same o (stride 8)
#pragma unroll
    for (int j = 0; j < NACC; j++) {
        float x = acc[j];
        x += __shfl_xor_sync(0xffffffffu, x, 8);
        x += __shfl_xor_sync(0xffffffffu, x, 16);
        acc[j] = x;
    }

    __shared__ float red[8 * 8 * NACC];   // [warp][o][j]
    __shared__ float s_tot[8][NACC];      // per-CTA (o, j) totals
    const int warp = tid >> 5;
    const int lane = tid & 31;
    if (lane < 8) {
#pragma unroll
        for (int j = 0; j < NACC; j++)
            red[(warp * 8 + lane) * NACC + j] = acc[j];
    }
    __syncthreads();

    // 8 o * 60 j = 480 tasks; sum the 8 warp partials (f64) -> CTA totals
    for (int task = tid; task < 8 * NACC; task += 256) {
        const int oo = task / NACC;
        const int j  = task - oo * NACC;
        double s = 0.0;
#pragma unroll
        for (int wp = 0; wp < 8; wp++)
            s += (double)red[(wp * 8 + oo) * NACC + j];
        s_tot[oo][j] = (float)s;
    }
    __syncthreads();

    // expand 60 -> 169 per o and atomically add this chunk's contribution.
    // out was zeroed by the memset node; entries with al==9 || be==9 stay 0.
    static const int imap[13] = {0,0,0, 1,1,1, 2,2,2, 0, 0,1,2};   // g-index
    static const int kmap[13] = {0,1,2, 0,1,2, 0,1,2, 0, 3,3,3};   // P-index
    static const int CIDX[3][3] = {{0,1,2},{1,3,4},{2,4,5}};
    static const int QIDX[4][4] = {{0,1,2,6},{1,3,4,7},{2,4,5,8},{6,7,8,9}};

    for (int task = tid; task < O_ * 169; task += 256) {
        const int oo = task / 169;
        const int t169 = task - oo * 169;
        const int al = t169 / 13;
        const int be = t169 - al * 13;
        if (al == 9 || be == 9) continue;
        const int j = CIDX[imap[al]][imap[be]] * 10 + QIDX[kmap[al]][kmap[be]];
        atomicAdd(&out[(b * O_ + oo) * 169 + t169], s_tot[oo][j]);
    }
}

extern "C" void kernel_launch(void* const* d_in, const int* in_sizes, int n_in,
                              void* d_out, int out_size)
{
    // Bind by size rank: w_pixel > obj > camera_matrix > coord_K — invariant
    // to metadata ordering and element-vs-byte units.
    int order[8];
    int m = (n_in < 8) ? n_in : 8;
    for (int i = 0; i < m; i++) order[i] = i;
    for (int i = 0; i < m; i++)
        for (int j = i + 1; j < m; j++)
            if ((long long)in_sizes[order[j]] > (long long)in_sizes[order[i]]) {
                int t = order[i]; order[i] = order[j]; order[j] = t;
            }

    const void* wpix   = d_in[order[0]];
    const void* obj    = d_in[m > 1 ? order[1] : 0];
    const void* cam    = d_in[m > 2 ? order[2] : 0];
    const void* coordK = d_in[m > 3 ? order[3] : 0];
    float* out = (float*)d_out;

    // zero the f32 output (graph memset node, DMA — no kernel-launch floor)
    cudaMemsetAsync(d_out, 0, (size_t)out_size * sizeof(float), 0);
    mtm_onepass_kernel<<<B_ * NCH, 256>>>(obj, wpix, cam, coordK, out);
}